// round 14
// baseline (speedup 1.0000x reference)
#include <cuda_runtime.h>
#include <math.h>

#define NB    32     // batch
#define LSEQ  1024
#define CH    34
#define D     256
#define NE    8
#define NP    4      // only first 4 patches survive the [:, :seq_len] slice
#define PL    16
#define PRED  96
#define NSEG  4      // stats segments (256 timesteps each)
#define NBLK  128    // persistent grid (<=148 SMs -> all co-resident)

// Scratch (device globals — no allocation allowed).
__device__ float g_red[NB][NSEG][2];
__device__ float g_sink[4];                   // dead store target (never read)
__device__ __align__(16) float g_partial[NB][NE][NP * D];
__device__ unsigned g_tick[2];                // monotonic grid-barrier tickets
__device__ unsigned g_rel[2];                 // completed generations

// ---------------------------------------------------------------------------
// helpers
// ---------------------------------------------------------------------------
__device__ __forceinline__ void cp16(void* dst_smem, const void* src) {
    unsigned saddr = (unsigned)__cvta_generic_to_shared(dst_smem);
    asm volatile("cp.async.cg.shared.global [%0], [%1], 16;\n"
                 :: "r"(saddr), "l"(src));
}
#define CP_COMMIT()  asm volatile("cp.async.commit_group;\n" ::: "memory")
#define CP_WAIT(n)   asm volatile("cp.async.wait_group %0;\n" :: "n"(n) : "memory")

// Monotonic grid barrier: safe across graph replays (counters never reset).
__device__ __forceinline__ void grid_bar(int i, int tid) {
    __syncthreads();
    if (tid == 0) {
        __threadfence();
        const unsigned t   = atomicAdd(&g_tick[i], 1u);
        const unsigned gen = t >> 7;                    // / NBLK
        if ((t & (NBLK - 1)) == NBLK - 1) atomicAdd(&g_rel[i], 1u);
        while (atomicAdd(&g_rel[i], 0u) < gen + 1u) __nanosleep(32);
    }
    __syncthreads();
    __threadfence();
}

// ---------------------------------------------------------------------------
// Persistent fused kernel.  grid = 128 blocks, 256 threads.
// smem layout (float4 units):
//   s_w[64*65] | s_xp[32*65] | s_wp[256*5] | s_wr[8*65] | s_be4[16] |
//   s_br4[2] | s_bp4[64] | floats s_xn[512], s_g[32]
// phase A reuses s_xp region for its reduction; phase C reuses it for s_t.
// ---------------------------------------------------------------------------
#define SMEM_BYTES (8258 * 16)

__global__ void __launch_bounds__(256)
k_all(const float* __restrict__ x,
      const float* __restrict__ W_proj,
      const float* __restrict__ b_proj,
      const float* __restrict__ W_router,
      const float* __restrict__ b_router,
      const float* __restrict__ W_experts,
      const float* __restrict__ b_experts,
      const float* __restrict__ W_head,
      const float* __restrict__ b_head,
      float* __restrict__ out) {
    extern __shared__ float4 smem4[];
    float4* s_w   = smem4;
    float4* s_xp  = smem4 + 4160;
    float4* s_wp  = smem4 + 6240;
    float4* s_wr  = smem4 + 7520;
    float4* s_be4 = smem4 + 8040;
    float4* s_br4 = smem4 + 8056;
    float4* s_bp4 = smem4 + 8058;
    float*  s_xn  = (float*)(smem4 + 8122);
    float*  s_g   = s_xn + 512;
    float*  s_xpf = (float*)s_xp;
    float*  s_red = (float*)s_xp;              // phase A scratch
    float*  s_t   = (float*)s_xp;              // phase C scratch
    const float* s_bef = (const float*)s_be4;
    const float* s_brf = (const float*)s_br4;
    const float* s_bpf = (const float*)s_bp4;

    const int blk  = blockIdx.x;
    const int tid  = threadIdx.x;
    const int warp = tid >> 5;
    const int lane = tid & 31;

    // block mapping
    const int e   = blk >> 4;                  // expert          (phase B)
    const int bt  = (blk >> 2) & 3;            // b-tile          (phase B)
    const int htb = blk & 3;                   // h-tile          (phase B)
    const int ba  = blk >> 2;                  // batch elem      (phase A/C)
    const int seg = blk & 3;                   // stats segment   (phase A)

    // ======== issue cp.async for phase B weights FIRST (overlaps phase A) ====
    const float4* Wp4 = reinterpret_cast<const float4*>(W_proj);
    #pragma unroll
    for (int i = 0; i < 4; i++) {
        const int g = tid + 256 * i;
        cp16(&s_wp[(g >> 2) * 5 + (g & 3)], &Wp4[g]);
    }
    const float4* Wr4 = reinterpret_cast<const float4*>(W_router);
    #pragma unroll
    for (int i = 0; i < 2; i++) {
        const int g = tid + 256 * i;
        cp16(&s_wr[(g >> 6) * 65 + (g & 63)], &Wr4[g]);
    }
    if (tid < 16) cp16(&s_be4[tid],
                       reinterpret_cast<const float4*>(b_experts + e * D + htb * 64) + tid);
    if (tid < 2)  cp16(&s_br4[tid], reinterpret_cast<const float4*>(b_router) + tid);
    if (tid < 64) cp16(&s_bp4[tid], reinterpret_cast<const float4*>(b_proj) + tid);
    CP_COMMIT();

    const float4* Wg = reinterpret_cast<const float4*>(W_experts);
    #pragma unroll
    for (int r = 0; r < 16; r++) {
        const int flat = r * 256 + tid;
        const int row = flat >> 6, col = flat & 63;
        cp16(&s_w[row * 65 + col], &Wg[(size_t)(e * D + htb * 64 + row) * 64 + col]);
    }
    CP_COMMIT();

    // ======== Phase A: coalesced partial stats + W_head L2 warm =============
    {
        float wacc = 0.f;
        if (tid < 192) {
            const float4 t = reinterpret_cast<const float4*>(W_head)[(size_t)blk * 192 + tid];
            wacc += t.x + t.y + t.z + t.w;
        }

        const float4* xs = reinterpret_cast<const float4*>(
            x + ((size_t)ba * LSEQ + seg * 256) * CH);
        float sum = 0.f, sq = 0.f;
        #pragma unroll
        for (int it = 0; it < 9; it++) {
            const int i = tid + it * 256;
            if (it < 8 || i < 2176) {
                const float4 v = xs[i];
                const int f = i * 4;
                #pragma unroll
                for (int j = 0; j < 4; j++) {
                    const float el = (j == 0) ? v.x : (j == 1) ? v.y : (j == 2) ? v.z : v.w;
                    if ((f + j) % CH == 2) { sum += el; sq += el * el; }
                }
            }
        }
        #pragma unroll
        for (int o = 16; o; o >>= 1) {
            sum += __shfl_xor_sync(0xffffffffu, sum, o);
            sq  += __shfl_xor_sync(0xffffffffu, sq,  o);
        }
        if (lane == 0) { s_red[warp] = sum; s_red[8 + warp] = sq; }
        __syncthreads();
        if (tid == 0) {
            float ts = 0.f, tq = 0.f;
            #pragma unroll
            for (int w = 0; w < 8; w++) { ts += s_red[w]; tq += s_red[8 + w]; }
            g_red[ba][seg][0] = ts;
            g_red[ba][seg][1] = tq;
        }
        if (wacc != wacc) g_sink[0] = wacc;    // keep warm loads (never fires)
    }

    grid_bar(0, tid);                          // all g_red visible

    // ======== Phase B: fused prologue + expert GEMM =========================
    {
        const int b = bt * 8 + warp;           // this warp's batch elem

        // x values (L2-hot from phase A) + stats partials
        const float v0 = x[(size_t)b * LSEQ * CH + (size_t)lane * CH + 2];
        const float v1 = x[(size_t)b * LSEQ * CH + (size_t)(lane + 32) * CH + 2];
        float rs = 0.f, rq = 0.f;
        if (lane < NSEG) { rs = g_red[b][lane][0]; rq = g_red[b][lane][1]; }
        #pragma unroll
        for (int o = 2; o; o >>= 1) {
            rs += __shfl_xor_sync(0xffffffffu, rs, o, 4);
            rq += __shfl_xor_sync(0xffffffffu, rq, o, 4);
        }
        rs = __shfl_sync(0xffffffffu, rs, 0);
        rq = __shfl_sync(0xffffffffu, rq, 0);
        const float mean = rs * (1.0f / LSEQ);
        const float var  = rq * (1.0f / LSEQ) - mean * mean;
        const float inv  = 1.0f / sqrtf(var + 1e-5f);

        s_xn[warp * 64 + lane]      = (v0 - mean) * inv;
        s_xn[warp * 64 + lane + 32] = (v1 - mean) * inv;

        CP_WAIT(1);          // small weights resident (long since, in practice)
        __syncthreads();

        // xp: lane computes d = lane + 32*dd for its warp's b
        const float* xnw = s_xn + warp * 64;
        #pragma unroll
        for (int dd = 0; dd < 8; dd++) {
            const int d = lane + dd * 32;
            float w[PL];
            #pragma unroll
            for (int q = 0; q < 4; q++) {
                const float4 t = s_wp[d * 5 + q];
                w[q * 4 + 0] = t.x; w[q * 4 + 1] = t.y;
                w[q * 4 + 2] = t.z; w[q * 4 + 3] = t.w;
            }
            const float bp = s_bpf[d];
            #pragma unroll
            for (int p = 0; p < NP; p++) {
                float acc = bp;
                #pragma unroll
                for (int k = 0; k < PL; k++) acc = fmaf(w[k], xnw[p * PL + k], acc);
                s_xpf[(warp * 4 + p) * 260 + d] = acc;
            }
        }
        __syncwarp();

        // router + softmax: lane = (p, ee) for this warp's b
        {
            const int p  = lane >> 3;
            const int ee = lane & 7;
            const float4* xrow = s_xp + (warp * 4 + p) * 65;
            const float4* wrow = s_wr + ee * 65;
            float a0 = 0.f, a1 = 0.f, a2 = 0.f, a3 = 0.f;
            #pragma unroll
            for (int k = 0; k < 64; k += 4) {
                const float4 w0 = wrow[k],     w1 = wrow[k + 1];
                const float4 w2 = wrow[k + 2], w3 = wrow[k + 3];
                const float4 x0 = xrow[k],     x1 = xrow[k + 1];
                const float4 x2 = xrow[k + 2], x3 = xrow[k + 3];
                a0 = fmaf(w0.x, x0.x, a0); a0 = fmaf(w0.y, x0.y, a0);
                a0 = fmaf(w0.z, x0.z, a0); a0 = fmaf(w0.w, x0.w, a0);
                a1 = fmaf(w1.x, x1.x, a1); a1 = fmaf(w1.y, x1.y, a1);
                a1 = fmaf(w1.z, x1.z, a1); a1 = fmaf(w1.w, x1.w, a1);
                a2 = fmaf(w2.x, x2.x, a2); a2 = fmaf(w2.y, x2.y, a2);
                a2 = fmaf(w2.z, x2.z, a2); a2 = fmaf(w2.w, x2.w, a2);
                a3 = fmaf(w3.x, x3.x, a3); a3 = fmaf(w3.y, x3.y, a3);
                a3 = fmaf(w3.z, x3.z, a3); a3 = fmaf(w3.w, x3.w, a3);
            }
            const float logit = (a0 + a1) + (a2 + a3) + s_brf[ee];
            float m = logit;
            #pragma unroll
            for (int o = 4; o; o >>= 1) m = fmaxf(m, __shfl_xor_sync(0xffffffffu, m, o, 8));
            const float exv = __expf(logit - m);
            float den = exv;
            #pragma unroll
            for (int o = 4; o; o >>= 1) den += __shfl_xor_sync(0xffffffffu, den, o, 8);
            if (ee == e) s_g[warp * 4 + p] = exv / den;
        }

        CP_WAIT(0);          // W tile resident
        __syncthreads();

        // GEMM: thread = (rt row-tile, ht strided-h, kh K-half)
        const int kh = tid & 1;
        const int ht = (tid >> 1) & 15;
        const int rt = tid >> 5;

        float acc[4][4];
        #pragma unroll
        for (int i = 0; i < 4; i++)
            #pragma unroll
            for (int j = 0; j < 4; j++) acc[i][j] = 0.f;

        const float4* xb4 = s_xp + rt * 4 * 65 + kh * 32;
        const float4* wb4 = s_w  + ht * 65     + kh * 32;

        #pragma unroll 4
        for (int kk = 0; kk < 32; kk++) {
            const float4 x0 = xb4[0 * 65 + kk];
            const float4 x1 = xb4[1 * 65 + kk];
            const float4 x2 = xb4[2 * 65 + kk];
            const float4 x3 = xb4[3 * 65 + kk];
            const float4 w0 = wb4[0 * 1040 + kk];
            const float4 w1 = wb4[1 * 1040 + kk];
            const float4 w2 = wb4[2 * 1040 + kk];
            const float4 w3 = wb4[3 * 1040 + kk];
            #pragma unroll
            for (int i = 0; i < 4; i++) {
                const float4 xv = (i == 0) ? x0 : (i == 1) ? x1 : (i == 2) ? x2 : x3;
                acc[i][0] = fmaf(xv.x, w0.x, acc[i][0]); acc[i][0] = fmaf(xv.y, w0.y, acc[i][0]);
                acc[i][0] = fmaf(xv.z, w0.z, acc[i][0]); acc[i][0] = fmaf(xv.w, w0.w, acc[i][0]);
                acc[i][1] = fmaf(xv.x, w1.x, acc[i][1]); acc[i][1] = fmaf(xv.y, w1.y, acc[i][1]);
                acc[i][1] = fmaf(xv.z, w1.z, acc[i][1]); acc[i][1] = fmaf(xv.w, w1.w, acc[i][1]);
                acc[i][2] = fmaf(xv.x, w2.x, acc[i][2]); acc[i][2] = fmaf(xv.y, w2.y, acc[i][2]);
                acc[i][2] = fmaf(xv.z, w2.z, acc[i][2]); acc[i][2] = fmaf(xv.w, w2.w, acc[i][2]);
                acc[i][3] = fmaf(xv.x, w3.x, acc[i][3]); acc[i][3] = fmaf(xv.y, w3.y, acc[i][3]);
                acc[i][3] = fmaf(xv.z, w3.z, acc[i][3]); acc[i][3] = fmaf(xv.w, w3.w, acc[i][3]);
            }
        }

        #pragma unroll
        for (int i = 0; i < 4; i++)
            #pragma unroll
            for (int j = 0; j < 4; j++)
                acc[i][j] += __shfl_xor_sync(0xffffffffu, acc[i][j], 1);

        if (kh == 0) {
            #pragma unroll
            for (int i = 0; i < 4; i++) {
                const int r  = rt * 4 + i;
                const int bb = bt * 8 + (r >> 2);
                const int p  = r & 3;
                const float g = s_g[r];
                #pragma unroll
                for (int j = 0; j < 4; j++) {
                    const int hl = ht + j * 16;
                    g_partial[bb][e][p * D + htb * 64 + hl] = g * (acc[i][j] + s_bef[hl]);
                }
            }
        }
    }

    grid_bar(1, tid);                          // all g_partial visible

    // ======== Phase C: combine + de-normalize + head matvec =================
    {
        const int ttile = blk & 3;             // 24 outputs per block

        // combine 8 experts (independent L2-hot LDG.128) + stats recompute
        const float4* gp = reinterpret_cast<const float4*>(&g_partial[ba][0][0]);
        float4 v[NE];
        #pragma unroll
        for (int ee = 0; ee < NE; ee++) v[ee] = gp[ee * 256 + tid];

        float ts = 0.f, tq = 0.f;
        #pragma unroll
        for (int s = 0; s < NSEG; s++) { ts += g_red[ba][s][0]; tq += g_red[ba][s][1]; }
        const float mean = ts * (1.0f / LSEQ);
        const float sd   = sqrtf(tq * (1.0f / LSEQ) - mean * mean + 1e-5f);

        float4 acc = v[0];
        #pragma unroll
        for (int ee = 1; ee < NE; ee++) {
            acc.x += v[ee].x; acc.y += v[ee].y; acc.z += v[ee].z; acc.w += v[ee].w;
        }
        reinterpret_cast<float4*>(s_t)[tid] =
            make_float4(fmaf(acc.x, sd, mean), fmaf(acc.y, sd, mean),
                        fmaf(acc.z, sd, mean), fmaf(acc.w, sd, mean));
        __syncthreads();

        // 8 warps x 3 outputs each
        const float4* tt = reinterpret_cast<const float4*>(s_t);
        float r0 = 0.f, r1 = 0.f, r2 = 0.f;
        const int t0 = ttile * 24 + warp * 3;
        const float4* w0r = reinterpret_cast<const float4*>(W_head + (size_t)(t0    ) * LSEQ);
        const float4* w1r = reinterpret_cast<const float4*>(W_head + (size_t)(t0 + 1) * LSEQ);
        const float4* w2r = reinterpret_cast<const float4*>(W_head + (size_t)(t0 + 2) * LSEQ);
        #pragma unroll
        for (int q = 0; q < 8; q++) {
            const int i = q * 32 + lane;
            const float4 f  = tt[i];
            const float4 a  = w0r[i];
            const float4 bq = w1r[i];
            const float4 c  = w2r[i];
            r0 = fmaf(a.x,  f.x, r0); r0 = fmaf(a.y,  f.y, r0);
            r0 = fmaf(a.z,  f.z, r0); r0 = fmaf(a.w,  f.w, r0);
            r1 = fmaf(bq.x, f.x, r1); r1 = fmaf(bq.y, f.y, r1);
            r1 = fmaf(bq.z, f.z, r1); r1 = fmaf(bq.w, f.w, r1);
            r2 = fmaf(c.x,  f.x, r2); r2 = fmaf(c.y,  f.y, r2);
            r2 = fmaf(c.z,  f.z, r2); r2 = fmaf(c.w,  f.w, r2);
        }
        #pragma unroll
        for (int o = 16; o; o >>= 1) {
            r0 += __shfl_xor_sync(0xffffffffu, r0, o);
            r1 += __shfl_xor_sync(0xffffffffu, r1, o);
            r2 += __shfl_xor_sync(0xffffffffu, r2, o);
        }
        if (lane == 0) {
            out[ba * PRED + t0    ] = r0 + b_head[t0];
            out[ba * PRED + t0 + 1] = r1 + b_head[t0 + 1];
            out[ba * PRED + t0 + 2] = r2 + b_head[t0 + 2];
        }
    }
}

// ---------------------------------------------------------------------------
extern "C" void kernel_launch(void* const* d_in, const int* in_sizes, int n_in,
                              void* d_out, int out_size) {
    const float* x         = (const float*)d_in[0];
    const float* W_proj    = (const float*)d_in[4];
    const float* b_proj    = (const float*)d_in[5];
    const float* W_router  = (const float*)d_in[6];
    const float* b_router  = (const float*)d_in[7];
    const float* W_experts = (const float*)d_in[8];
    const float* b_experts = (const float*)d_in[9];
    const float* W_head    = (const float*)d_in[10];
    const float* b_head    = (const float*)d_in[11];
    float* out = (float*)d_out;

    cudaFuncSetAttribute(k_all,
                         cudaFuncAttributeMaxDynamicSharedMemorySize,
                         SMEM_BYTES);

    k_all<<<NBLK, 256, SMEM_BYTES>>>(x, W_proj, b_proj, W_router, b_router,
                                     W_experts, b_experts, W_head, b_head, out);
}

// round 15
// speedup vs baseline: 1.1863x; 1.1863x over previous
#include <cuda_runtime.h>
#include <math.h>

#define NB    32     // batch
#define LSEQ  1024
#define CH    34
#define D     256
#define NE    8
#define NP    4      // only first 4 patches survive the [:, :seq_len] slice
#define PL    16
#define PRED  96
#define NSEG  4      // stats segments (256 timesteps each)

// Scratch (device globals — no allocation allowed). 16B-aligned for float4 IO.
__device__ float g_red[NB][NSEG][2];          // per-segment partial sums
__device__ float g_sink[4];                   // dead store target (never read)
__device__ __align__(16) float g_xp[NB][NP][D];
__device__ __align__(16) float g_gates[NB][NP][NE];
__device__ __align__(16) float g_partial[NB][NE][NP * D];

// ---------------------------------------------------------------------------
// cp.async helpers (LDGSTS)
// ---------------------------------------------------------------------------
__device__ __forceinline__ void cp16(void* dst_smem, const void* src) {
    unsigned saddr = (unsigned)__cvta_generic_to_shared(dst_smem);
    asm volatile("cp.async.cg.shared.global [%0], [%1], 16;\n"
                 :: "r"(saddr), "l"(src));
}
#define CP_COMMIT()  asm volatile("cp.async.commit_group;\n" ::: "memory")
#define CP_WAIT(n)   asm volatile("cp.async.wait_group %0;\n" :: "n"(n) : "memory")

// ---------------------------------------------------------------------------
// K0: COALESCED partial stats over x[b,:,2] + L2 warm of W_experts / W_head.
// grid = 128 blocks (b*4 + seg), 256 threads.   (round-13 proven)
// ---------------------------------------------------------------------------
__global__ void __launch_bounds__(256)
k0_stats(const float* __restrict__ x,
         const float* __restrict__ W_experts,
         const float* __restrict__ W_head) {
    const int blk = blockIdx.x;
    const int b   = blk >> 2;
    const int seg = blk & 3;
    const int tid  = threadIdx.x;
    const int warp = tid >> 5;
    const int lane = tid & 31;

    __shared__ float sred[16];

    // L2 warm (independent coalesced loads; overlap with x streaming)
    float wacc = 0.f;
    {
        const float4* we4 = reinterpret_cast<const float4*>(W_experts);
        #pragma unroll
        for (int i = 0; i < 4; i++) {
            const float4 t = we4[(size_t)blk * 1024 + i * 256 + tid];
            wacc += t.x + t.y + t.z + t.w;
        }
        if (tid < 192) {
            const float4 t = reinterpret_cast<const float4*>(W_head)[(size_t)blk * 192 + tid];
            wacc += t.x + t.y + t.z + t.w;
        }
    }

    // coalesced x chunk: floats [base, base+8704), base divisible by 34
    const float4* xs = reinterpret_cast<const float4*>(
        x + ((size_t)b * LSEQ + seg * 256) * CH);
    float sum = 0.f, sq = 0.f;
    #pragma unroll
    for (int it = 0; it < 9; it++) {
        const int i = tid + it * 256;
        if (it < 8 || i < 2176) {
            const float4 v = xs[i];
            const int f = i * 4;
            #pragma unroll
            for (int j = 0; j < 4; j++) {
                const float el = (j == 0) ? v.x : (j == 1) ? v.y : (j == 2) ? v.z : v.w;
                if ((f + j) % CH == 2) { sum += el; sq += el * el; }
            }
        }
    }

    cudaTriggerProgrammaticLaunchCompletion();   // let k1 spin up

    #pragma unroll
    for (int o = 16; o; o >>= 1) {
        sum += __shfl_xor_sync(0xffffffffu, sum, o);
        sq  += __shfl_xor_sync(0xffffffffu, sq,  o);
    }
    if (lane == 0) { sred[warp] = sum; sred[8 + warp] = sq; }
    __syncthreads();
    if (tid == 0) {
        float ts = 0.f, tq = 0.f;
        #pragma unroll
        for (int w = 0; w < 8; w++) { ts += sred[w]; tq += sred[8 + w]; }
        g_red[b][seg][0] = ts;
        g_red[b][seg][1] = tq;
    }
    if (wacc != wacc) g_sink[0] = wacc;   // keep warm loads (never fires)
}

// ---------------------------------------------------------------------------
// K1: finalize stats + patch projection + router gates. grid=32, 256 thr.
// PDL: x-load + W_proj load pre-GDS; g_red read post-GDS.
// ---------------------------------------------------------------------------
__global__ void __launch_bounds__(256)
k1_prep(const float* __restrict__ x,
        const float* __restrict__ W_proj,
        const float* __restrict__ b_proj,
        const float* __restrict__ W_router,
        const float* __restrict__ b_router) {
    const int b    = blockIdx.x;
    const int tid  = threadIdx.x;
    const int warp = tid >> 5;
    const int lane = tid & 31;

    __shared__ __align__(16) float s_xn[NP * PL];
    __shared__ __align__(16) float s_xp[NP * D];
    __shared__ float s_logit[NP * NE];
    __shared__ float s_mean, s_inv;

    // ---- pre-GDS prologue: input x + weights (independent of k0) ----
    float v = 0.f;
    if (tid < NP * PL)
        v = x[(size_t)b * LSEQ * CH + (size_t)tid * CH + 2];

    float w[PL];
    {
        const float4* wr4 = reinterpret_cast<const float4*>(W_proj + tid * PL);
        #pragma unroll
        for (int q = 0; q < 4; q++) {
            const float4 t = wr4[q];
            w[q * 4 + 0] = t.x; w[q * 4 + 1] = t.y; w[q * 4 + 2] = t.z; w[q * 4 + 3] = t.w;
        }
    }
    const float bp = b_proj[tid];

    cudaGridDependencySynchronize();            // wait for k0's g_red

    if (tid == 0) {
        float ts = 0.f, tq = 0.f;
        #pragma unroll
        for (int s = 0; s < NSEG; s++) { ts += g_red[b][s][0]; tq += g_red[b][s][1]; }
        const float mean = ts * (1.0f / LSEQ);
        const float var  = tq * (1.0f / LSEQ) - mean * mean;
        const float sd   = sqrtf(var + 1e-5f);
        s_mean = mean; s_inv = 1.0f / sd;
    }
    __syncthreads();

    if (tid < NP * PL) s_xn[tid] = (v - s_mean) * s_inv;
    __syncthreads();

    // ---- xp[p][d], d = tid ----
    #pragma unroll
    for (int p = 0; p < NP; p++) {
        float acc = bp;
        #pragma unroll
        for (int k = 0; k < PL; k++) acc = fmaf(w[k], s_xn[p * PL + k], acc);
        s_xp[p * D + tid] = acc;
    }
    __syncthreads();

    // publish xp (float4)
    reinterpret_cast<float4*>(&g_xp[b][0][0])[tid] =
        reinterpret_cast<const float4*>(s_xp)[tid & 255];

    // ---- router logits: 8 warps x 4 pi each ----
    #pragma unroll
    for (int r = 0; r < 4; r++) {
        const int pi = warp * 4 + r;            // pi = p*8 + e
        const int p  = pi >> 3, e = pi & 7;
        const float* wr = W_router + e * D;
        float acc = 0.f;
        #pragma unroll
        for (int q = 0; q < D / 32; q++) {
            const int d = lane + q * 32;
            acc = fmaf(wr[d], s_xp[p * D + d], acc);
        }
        #pragma unroll
        for (int o = 16; o; o >>= 1) acc += __shfl_xor_sync(0xffffffffu, acc, o);
        if (lane == 0) s_logit[pi] = acc + b_router[e];
    }
    __syncthreads();

    if (tid < NP) {
        const int p = tid;
        float m = s_logit[p * NE];
        #pragma unroll
        for (int j = 1; j < NE; j++) m = fmaxf(m, s_logit[p * NE + j]);
        float denom = 0.f;
        float ex[NE];
        #pragma unroll
        for (int j = 0; j < NE; j++) { ex[j] = __expf(s_logit[p * NE + j] - m); denom += ex[j]; }
        const float inv = 1.0f / denom;
        #pragma unroll
        for (int j = 0; j < NE; j++) g_gates[b][p][j] = ex[j] * inv;
    }
}

// ---------------------------------------------------------------------------
// K2: per-expert smem GEMM.  grid = (8 e, 4 b-tiles, 4 h-tiles), 256 threads.
// PDL: W tile + biases via cp.async pre-GDS (overlaps k1); xp/gates post-GDS.
// ---------------------------------------------------------------------------
#define K2_SMEM_BYTES ((64 * 65 + 32 * 65 + 16) * 16 + 32 * 4)

__global__ void __launch_bounds__(256)
k2_experts(const float* __restrict__ W_experts,
           const float* __restrict__ b_experts) {
    extern __shared__ float4 smem4[];
    float4* s_w   = smem4;                      // 64 rows x 65 float4
    float4* s_xp  = smem4 + 64 * 65;            // 32 rows x 65 float4
    float4* s_be4 = smem4 + 96 * 65;            // 16 float4 biases
    float*  s_g   = (float*)(smem4 + 96 * 65 + 16);  // 32 gates
    const float* s_be = (const float*)s_be4;

    const int e   = blockIdx.x;
    const int bt  = blockIdx.y;
    const int htb = blockIdx.z;
    const int tid = threadIdx.x;

    // ---- pre-GDS: weight fetch via cp.async (independent of k1) ----
    const float4* Wg = reinterpret_cast<const float4*>(W_experts);
    #pragma unroll
    for (int r = 0; r < 16; r++) {
        const int flat = r * 256 + tid;
        const int row = flat >> 6, col = flat & 63;
        cp16(&s_w[row * 65 + col], &Wg[(size_t)(e * D + htb * 64 + row) * 64 + col]);
    }
    if (tid < 16) cp16(&s_be4[tid],
                       reinterpret_cast<const float4*>(b_experts + e * D + htb * 64) + tid);
    CP_COMMIT();

    cudaGridDependencySynchronize();            // wait for k1's g_xp/g_gates

    const float4* Xg = reinterpret_cast<const float4*>(g_xp);
    #pragma unroll
    for (int r = 0; r < 8; r++) {
        const int flat = r * 256 + tid;
        const int row = flat >> 6, col = flat & 63;
        s_xp[row * 65 + col] = Xg[(bt * 8 * NP + row) * 64 + col];
    }
    if (tid < 32) {
        const int bl = tid >> 2, p = tid & 3;
        s_g[tid] = g_gates[bt * 8 + bl][p][e];
    }
    CP_WAIT(0);
    __syncthreads();

    cudaTriggerProgrammaticLaunchCompletion();  // let k3 spin up + prefetch

    const int kh = tid & 1;
    const int ht = (tid >> 1) & 15;
    const int rt = tid >> 5;

    float acc[4][4];
    #pragma unroll
    for (int i = 0; i < 4; i++)
        #pragma unroll
        for (int j = 0; j < 4; j++) acc[i][j] = 0.f;

    const float4* xb4 = s_xp + rt * 4 * 65 + kh * 32;
    const float4* wb4 = s_w  + ht * 65     + kh * 32;

    #pragma unroll 4
    for (int kk = 0; kk < 32; kk++) {
        const float4 x0 = xb4[0 * 65 + kk];
        const float4 x1 = xb4[1 * 65 + kk];
        const float4 x2 = xb4[2 * 65 + kk];
        const float4 x3 = xb4[3 * 65 + kk];
        const float4 w0 = wb4[0 * 1040 + kk];
        const float4 w1 = wb4[1 * 1040 + kk];
        const float4 w2 = wb4[2 * 1040 + kk];
        const float4 w3 = wb4[3 * 1040 + kk];
        #pragma unroll
        for (int i = 0; i < 4; i++) {
            const float4 xv = (i == 0) ? x0 : (i == 1) ? x1 : (i == 2) ? x2 : x3;
            acc[i][0] = fmaf(xv.x, w0.x, acc[i][0]); acc[i][0] = fmaf(xv.y, w0.y, acc[i][0]);
            acc[i][0] = fmaf(xv.z, w0.z, acc[i][0]); acc[i][0] = fmaf(xv.w, w0.w, acc[i][0]);
            acc[i][1] = fmaf(xv.x, w1.x, acc[i][1]); acc[i][1] = fmaf(xv.y, w1.y, acc[i][1]);
            acc[i][1] = fmaf(xv.z, w1.z, acc[i][1]); acc[i][1] = fmaf(xv.w, w1.w, acc[i][1]);
            acc[i][2] = fmaf(xv.x, w2.x, acc[i][2]); acc[i][2] = fmaf(xv.y, w2.y, acc[i][2]);
            acc[i][2] = fmaf(xv.z, w2.z, acc[i][2]); acc[i][2] = fmaf(xv.w, w2.w, acc[i][2]);
            acc[i][3] = fmaf(xv.x, w3.x, acc[i][3]); acc[i][3] = fmaf(xv.y, w3.y, acc[i][3]);
            acc[i][3] = fmaf(xv.z, w3.z, acc[i][3]); acc[i][3] = fmaf(xv.w, w3.w, acc[i][3]);
        }
    }

    #pragma unroll
    for (int i = 0; i < 4; i++)
        #pragma unroll
        for (int j = 0; j < 4; j++)
            acc[i][j] += __shfl_xor_sync(0xffffffffu, acc[i][j], 1);

    if (kh == 0) {
        #pragma unroll
        for (int i = 0; i < 4; i++) {
            const int r = rt * 4 + i;
            const int b = bt * 8 + (r >> 2);
            const int p = r & 3;
            const float g = s_g[r];
            #pragma unroll
            for (int j = 0; j < 4; j++) {
                const int hl = ht + j * 16;
                g_partial[b][e][p * D + htb * 64 + hl] = g * (acc[i][j] + s_be[hl]);
            }
        }
    }
}

// ---------------------------------------------------------------------------
// K3: combine 8 experts + de-normalize + head matvec.
// grid = (32 b, 12 t-tiles), 256 threads; 8 warps -> 8 outputs per block.
// PDL: this block's 8 W_head rows (32 KB) via cp.async pre-GDS (overlaps k2).
// ---------------------------------------------------------------------------
#define K3_SMEM_BYTES ((8 * 256 + 256) * 16)

__global__ void __launch_bounds__(256)
k3_head(const float* __restrict__ W_head,
        const float* __restrict__ b_head,
        float* __restrict__ out) {
    extern __shared__ float4 smem4[];
    float4* s_wh = smem4;            // 8 rows x 256 float4 (32 KB)
    float4* s_t4 = smem4 + 2048;     // 256 float4 (4 KB)
    float*  s_t  = (float*)s_t4;

    const int b    = blockIdx.x;
    const int tid  = threadIdx.x;
    const int warp = tid >> 5;
    const int lane = tid & 31;

    // ---- pre-GDS: prefetch this block's W_head rows (L2-warm from k0) ----
    const float4* whg = reinterpret_cast<const float4*>(W_head)
                      + (size_t)(blockIdx.y * 8) * 256;
    #pragma unroll
    for (int i = 0; i < 8; i++) cp16(&s_wh[i * 256 + tid], &whg[i * 256 + tid]);
    CP_COMMIT();

    cudaGridDependencySynchronize();            // wait for k2's g_partial

    // combine 8 experts (independent L2-hot LDG.128) + stats recompute
    const float4* gp = reinterpret_cast<const float4*>(&g_partial[b][0][0]);
    float4 v[NE];
    #pragma unroll
    for (int e = 0; e < NE; e++) v[e] = gp[e * 256 + tid];

    float ts = 0.f, tq = 0.f;
    #pragma unroll
    for (int s = 0; s < NSEG; s++) { ts += g_red[b][s][0]; tq += g_red[b][s][1]; }
    const float mean = ts * (1.0f / LSEQ);
    const float sd   = sqrtf(tq * (1.0f / LSEQ) - mean * mean + 1e-5f);

    float4 acc = v[0];
    #pragma unroll
    for (int e = 1; e < NE; e++) {
        acc.x += v[e].x; acc.y += v[e].y; acc.z += v[e].z; acc.w += v[e].w;
    }
    s_t4[tid] = make_float4(fmaf(acc.x, sd, mean), fmaf(acc.y, sd, mean),
                            fmaf(acc.z, sd, mean), fmaf(acc.w, sd, mean));
    CP_WAIT(0);
    __syncthreads();

    const int t = blockIdx.y * 8 + warp;
    const float4* wr = s_wh + warp * 256;
    float ax = 0.f, ay = 0.f, az = 0.f, aw = 0.f;
    #pragma unroll
    for (int q = 0; q < 8; q++) {
        const int i = q * 32 + lane;
        const float4 w = wr[i];
        const float4 f = s_t4[i];
        ax = fmaf(w.x, f.x, ax);
        ay = fmaf(w.y, f.y, ay);
        az = fmaf(w.z, f.z, az);
        aw = fmaf(w.w, f.w, aw);
    }
    float r = (ax + ay) + (az + aw);
    #pragma unroll
    for (int o = 16; o; o >>= 1) r += __shfl_xor_sync(0xffffffffu, r, o);
    if (lane == 0) out[b * PRED + t] = r + b_head[t];
}

// ---------------------------------------------------------------------------
extern "C" void kernel_launch(void* const* d_in, const int* in_sizes, int n_in,
                              void* d_out, int out_size) {
    const float* x         = (const float*)d_in[0];
    const float* W_proj    = (const float*)d_in[4];
    const float* b_proj    = (const float*)d_in[5];
    const float* W_router  = (const float*)d_in[6];
    const float* b_router  = (const float*)d_in[7];
    const float* W_experts = (const float*)d_in[8];
    const float* b_experts = (const float*)d_in[9];
    const float* W_head    = (const float*)d_in[10];
    const float* b_head    = (const float*)d_in[11];
    float* out = (float*)d_out;

    cudaFuncSetAttribute(k2_experts,
                         cudaFuncAttributeMaxDynamicSharedMemorySize, K2_SMEM_BYTES);
    cudaFuncSetAttribute(k3_head,
                         cudaFuncAttributeMaxDynamicSharedMemorySize, K3_SMEM_BYTES);

    // k0: plain launch
    k0_stats<<<NB * NSEG, 256>>>(x, W_experts, W_head);

    cudaLaunchAttribute pdl[1];
    pdl[0].id = cudaLaunchAttributeProgrammaticStreamSerialization;
    pdl[0].val.programmaticStreamSerializationAllowed = 1;

    // k1 (PDL after k0)
    {
        cudaLaunchConfig_t cfg = {};
        cfg.gridDim = dim3(NB); cfg.blockDim = dim3(256);
        cfg.dynamicSmemBytes = 0; cfg.attrs = pdl; cfg.numAttrs = 1;
        void* args[] = {(void*)&x, (void*)&W_proj, (void*)&b_proj,
                        (void*)&W_router, (void*)&b_router};
        cudaLaunchKernelExC(&cfg, (const void*)k1_prep, args);
    }
    // k2 (PDL after k1)
    {
        cudaLaunchConfig_t cfg = {};
        cfg.gridDim = dim3(NE, NB / 8, NP); cfg.blockDim = dim3(256);
        cfg.dynamicSmemBytes = K2_SMEM_BYTES; cfg.attrs = pdl; cfg.numAttrs = 1;
        void* args[] = {(void*)&W_experts, (void*)&b_experts};
        cudaLaunchKernelExC(&cfg, (const void*)k2_experts, args);
    }
    // k3 (PDL after k2)
    {
        cudaLaunchConfig_t cfg = {};
        cfg.gridDim = dim3(NB, PRED / 8); cfg.blockDim = dim3(256);
        cfg.dynamicSmemBytes = K3_SMEM_BYTES; cfg.attrs = pdl; cfg.numAttrs = 1;
        void* args[] = {(void*)&W_head, (void*)&b_head, (void*)&out};
        cudaLaunchKernelExC(&cfg, (const void*)k3_head, args);
    }
}